// round 1
// baseline (speedup 1.0000x reference)
#include <cuda_runtime.h>
#include <math.h>

#define B_   8
#define N_   8192
#define C_   256
#define H_   128
#define W_   128
#define NH_  8
#define NP_  4
#define D_   32
#define HW_  (H_ * W_)
#define M_   (B_ * N_)      // 65536
#define P96  96

// ---- scratch (static device allocations; no cudaMalloc anywhere) ----
__device__ float g_valt[(size_t)B_ * NH_ * HW_ * D_];   // value transposed to (B,Hh,HW,D)  ~134MB
__device__ float g_params[(size_t)M_ * P96];            // [offsets(64) | attn logits(32)]   ~25MB
__device__ float g_agg[(size_t)M_ * C_];                // attention-aggregated features     ~67MB
__device__ float g_wcat[C_ * P96];
__device__ float g_bcat[P96];

// ---------------------------------------------------------------------------
// Concatenate W_off (256x64) and W_attn (256x32) into one 256x96 weight,
// so the projection is a single GEMM.
// ---------------------------------------------------------------------------
__global__ void concat_w_kernel(const float* __restrict__ W_off,
                                const float* __restrict__ b_off,
                                const float* __restrict__ W_attn,
                                const float* __restrict__ b_attn) {
    int i = blockIdx.x * blockDim.x + threadIdx.x;
    if (i < C_ * P96) {
        int k = i / P96, j = i % P96;
        g_wcat[i] = (j < 64) ? W_off[k * 64 + j] : W_attn[k * 32 + (j - 64)];
    }
    if (i < P96) g_bcat[i] = (i < 64) ? b_off[i] : b_attn[i - 64];
}

// ---------------------------------------------------------------------------
// Transpose value (B, C=Hh*D, H*W) -> (B, Hh, H*W, D) so that bilinear
// corner gathers are D-contiguous (one 128B line per corner per warp).
// c = h*32 + d, and (b*256 + h*32) == (b*8+h)*32, so blockIdx.y == b*8+h.
// ---------------------------------------------------------------------------
__global__ void transpose_val_kernel(const float* __restrict__ val) {
    __shared__ float t[32][33];
    int bh = blockIdx.y;                 // b*8 + h
    int p0 = blockIdx.x * 32;            // position tile
    const float* src = val + ((size_t)bh * 32) * HW_ + p0;
    for (int d = threadIdx.y; d < 32; d += 8)
        t[d][threadIdx.x] = src[(size_t)d * HW_ + threadIdx.x];
    __syncthreads();
    float* dst = g_valt + (size_t)bh * HW_ * D_ + (size_t)p0 * D_;
    for (int dp = threadIdx.y; dp < 32; dp += 8)
        dst[(size_t)dp * D_ + threadIdx.x] = t[threadIdx.x][dp];
}

// ---------------------------------------------------------------------------
// fp32 SIMT GEMM: C[M,Nn] = A[M,K] @ B[K,Nn] + bias.  BM=128 BN=64 BK=16,
// 256 threads, 8x4 register microtile, float4 global + shared paths.
// M divisible by 128, K by 16; only Nn needs bounds (96 case).
// ---------------------------------------------------------------------------
#define BM 128
#define BN 64
#define BK 16
#define TM 8
#define TN 4

__device__ __forceinline__ void sgemm_body(const float* __restrict__ A,
                                           const float* __restrict__ Bw,
                                           const float* __restrict__ bias,
                                           float* __restrict__ Cm,
                                           int Nn, int K) {
    __shared__ float As[BK][BM];
    __shared__ float Bs[BK][BN];
    const int tid  = threadIdx.x;
    const int row0 = blockIdx.y * BM;
    const int col0 = blockIdx.x * BN;
    const int tr   = tid >> 4;          // 0..15 -> rows tr*8..tr*8+7
    const int tc   = tid & 15;          // 0..15 -> cols tc*4..tc*4+3

    float acc[TM][TN];
#pragma unroll
    for (int i = 0; i < TM; i++)
#pragma unroll
        for (int j = 0; j < TN; j++) acc[i][j] = 0.f;

    const int ar = tid >> 1;            // 0..127
    const int ac = (tid & 1) * 8;       // 0 or 8
    const int br = tid >> 4;            // 0..15
    const int bc = (tid & 15) * 4;      // 0..60

    for (int k0 = 0; k0 < K; k0 += BK) {
        const float* ap = &A[(size_t)(row0 + ar) * K + k0 + ac];
        float4 a0 = *(const float4*)(ap);
        float4 a1 = *(const float4*)(ap + 4);
        As[ac + 0][ar] = a0.x; As[ac + 1][ar] = a0.y;
        As[ac + 2][ar] = a0.z; As[ac + 3][ar] = a0.w;
        As[ac + 4][ar] = a1.x; As[ac + 5][ar] = a1.y;
        As[ac + 6][ar] = a1.z; As[ac + 7][ar] = a1.w;

        float4 bv = make_float4(0.f, 0.f, 0.f, 0.f);
        if (col0 + bc < Nn)
            bv = *(const float4*)&Bw[(size_t)(k0 + br) * Nn + col0 + bc];
        *(float4*)&Bs[br][bc] = bv;

        __syncthreads();
#pragma unroll
        for (int kk = 0; kk < BK; kk++) {
            float4 b4  = *(const float4*)&Bs[kk][tc * TN];
            float4 af0 = *(const float4*)&As[kk][tr * TM];
            float4 af1 = *(const float4*)&As[kk][tr * TM + 4];
            float a8[TM] = {af0.x, af0.y, af0.z, af0.w, af1.x, af1.y, af1.z, af1.w};
            float b4a[TN] = {b4.x, b4.y, b4.z, b4.w};
#pragma unroll
            for (int i = 0; i < TM; i++)
#pragma unroll
                for (int j = 0; j < TN; j++)
                    acc[i][j] = fmaf(a8[i], b4a[j], acc[i][j]);
        }
        __syncthreads();
    }

#pragma unroll
    for (int i = 0; i < TM; i++) {
        int r = row0 + tr * TM + i;
#pragma unroll
        for (int j = 0; j < TN; j++) {
            int c = col0 + tc * TN + j;
            if (c < Nn)
                Cm[(size_t)r * Nn + c] = acc[i][j] + bias[c];
        }
    }
}

__global__ void gemm_params_kernel(const float* __restrict__ query) {
    sgemm_body(query, g_wcat, g_bcat, g_params, P96, C_);
}

__global__ void gemm_out_kernel(const float* __restrict__ Wo,
                                const float* __restrict__ bo,
                                float* __restrict__ out) {
    sgemm_body(g_agg, Wo, bo, out, C_, C_);
}

// ---------------------------------------------------------------------------
// Sampling: warp <-> (b, n, head); lane <-> d (D == 32 == warpsize).
// Each warp: softmax over P=4 logits, then 4 points x 4 bilinear corners,
// each corner one coalesced 128B gather from g_valt.
// ---------------------------------------------------------------------------
__global__ void sample_kernel(const float* __restrict__ refp) {
    int gw   = (blockIdx.x * blockDim.x + threadIdx.x) >> 5;
    int lane = threadIdx.x & 31;
    if (gw >= B_ * N_ * NH_) return;
    int h  = gw & 7;
    int bn = gw >> 3;            // b*N + n
    int b  = bn >> 13;           // N = 8192 = 2^13

    const float* pr = g_params + (size_t)bn * P96;

    float rx = refp[2 * bn], ry = refp[2 * bn + 1];
    // x = ((2*rx - 1) + off + 1) * W/2 - 0.5 = (2*rx + off)*W/2 - 0.5
    float bx = 2.f * rx;
    float by = 2.f * ry;

    const float* al = pr + 64 + h * 4;
    float l0 = al[0], l1 = al[1], l2 = al[2], l3 = al[3];
    float mx = fmaxf(fmaxf(l0, l1), fmaxf(l2, l3));
    float e0 = __expf(l0 - mx), e1 = __expf(l1 - mx);
    float e2 = __expf(l2 - mx), e3 = __expf(l3 - mx);
    float inv = 1.f / (e0 + e1 + e2 + e3);
    float aw[4] = {e0 * inv, e1 * inv, e2 * inv, e3 * inv};

    const float* vb = g_valt + (size_t)(b * NH_ + h) * HW_ * D_ + lane;
    float acc = 0.f;
#pragma unroll
    for (int p = 0; p < 4; p++) {
        float ox = pr[(h * 4 + p) * 2];
        float oy = pr[(h * 4 + p) * 2 + 1];
        float x = fmaf(bx + ox, (float)W_ * 0.5f, -0.5f);
        float y = fmaf(by + oy, (float)H_ * 0.5f, -0.5f);
        float x0f = floorf(x), y0f = floorf(y);
        float wx = x - x0f, wy = y - y0f;
        int x0 = (int)x0f, y0 = (int)y0f;
        int x1 = x0 + 1,  y1 = y0 + 1;
        bool vx0 = (x0 >= 0) & (x0 < W_), vx1 = (x1 >= 0) & (x1 < W_);
        bool vy0 = (y0 >= 0) & (y0 < H_), vy1 = (y1 >= 0) & (y1 < H_);
        float v00 = (vx0 && vy0) ? vb[(size_t)(y0 * W_ + x0) * D_] : 0.f;
        float v10 = (vx1 && vy0) ? vb[(size_t)(y0 * W_ + x1) * D_] : 0.f;
        float v01 = (vx0 && vy1) ? vb[(size_t)(y1 * W_ + x0) * D_] : 0.f;
        float v11 = (vx1 && vy1) ? vb[(size_t)(y1 * W_ + x1) * D_] : 0.f;
        float s = (v00 * (1.f - wx) + v10 * wx) * (1.f - wy)
                + (v01 * (1.f - wx) + v11 * wx) * wy;
        acc = fmaf(aw[p], s, acc);
    }
    g_agg[(size_t)bn * C_ + h * D_ + lane] = acc;
}

// ---------------------------------------------------------------------------
extern "C" void kernel_launch(void* const* d_in, const int* in_sizes, int n_in,
                              void* d_out, int out_size) {
    const float* query  = (const float*)d_in[0];
    const float* refp   = (const float*)d_in[1];
    const float* value  = (const float*)d_in[2];
    const float* W_off  = (const float*)d_in[3];
    const float* b_off  = (const float*)d_in[4];
    const float* W_attn = (const float*)d_in[5];
    const float* b_attn = (const float*)d_in[6];
    const float* W_out  = (const float*)d_in[7];
    const float* b_out  = (const float*)d_in[8];
    float* out = (float*)d_out;

    concat_w_kernel<<<(C_ * P96 + 255) / 256, 256>>>(W_off, b_off, W_attn, b_attn);
    transpose_val_kernel<<<dim3(HW_ / 32, B_ * NH_), dim3(32, 8)>>>(value);
    gemm_params_kernel<<<dim3((P96 + BN - 1) / BN, M_ / BM), 256>>>(query);
    sample_kernel<<<(B_ * N_ * NH_ * 32) / 256, 256>>>(refp);
    gemm_out_kernel<<<dim3(C_ / BN, M_ / BM), 256>>>(W_out, b_out, out);
}